// round 6
// baseline (speedup 1.0000x reference)
#include <cuda_runtime.h>
#include <cuda_fp16.h>
#include <cstdint>

// ---------------- problem constants ----------------
#define YTRUE_OFF  33505280l
#define YTRUE_SIZE 261760l
#define ACC_OFF    33767040l

// ---------------- scratch (__device__ globals; no allocs allowed) ----------------
static __device__ __half g_ts16[128ll * 1024 * 512];        // timesteps f16
static __device__ __half g_pt16[128ll * 1024 * 512];        // patient f16
static __device__ __half g_pred16[2ll * 128 * 1024 * 512];  // pred f16 [step][m][l][c]
static __device__ __half g_w16[2ll * 512 * 512];            // W1,W2 f16
static __device__ float  g_lneg[2045ll * 128 * 128];        // [gl][n*128+m]
static __device__ unsigned int g_cnt[2];

// ---------------- PTX helpers (family-portable; no tcgen05) ----------------
__device__ __forceinline__ uint32_t s2u(const void* p) {
    uint32_t a;
    asm("{ .reg .u64 t; cvta.to.shared.u64 t, %1; cvt.u32.u64 %0, t; }" : "=r"(a) : "l"(p));
    return a;
}
__device__ __forceinline__ void cp16(uint32_t dst, const void* src) {
    asm volatile("cp.async.cg.shared.global [%0], [%1], 16;" :: "r"(dst), "l"(src));
}
#define CP_COMMIT() asm volatile("cp.async.commit_group;" ::: "memory")
#define CP_WAIT1()  asm volatile("cp.async.wait_group 1;" ::: "memory")
#define CP_WAIT0()  asm volatile("cp.async.wait_group 0;" ::: "memory")

__device__ __forceinline__ void ldsm4(uint32_t addr, uint32_t& r0, uint32_t& r1,
                                      uint32_t& r2, uint32_t& r3) {
    asm volatile("ldmatrix.sync.aligned.m8n8.x4.shared.b16 {%0,%1,%2,%3}, [%4];"
                 : "=r"(r0), "=r"(r1), "=r"(r2), "=r"(r3) : "r"(addr));
}
__device__ __forceinline__ void mma16816(float* d, const uint32_t* a, uint32_t b0, uint32_t b1) {
    asm volatile(
        "mma.sync.aligned.m16n8k16.row.col.f32.f16.f16.f32 "
        "{%0,%1,%2,%3}, {%4,%5,%6,%7}, {%8,%9}, {%0,%1,%2,%3};"
        : "+f"(d[0]), "+f"(d[1]), "+f"(d[2]), "+f"(d[3])
        : "r"(a[0]), "r"(a[1]), "r"(a[2]), "r"(a[3]), "r"(b0), "r"(b1));
}

// ---------------- stage geometry ----------------
#define ROWB   144u                  // 64 halves + 16B pad
#define MATB   (128u * ROWB)         // 18432
#define STB    (2u * MATB)           // 36864 (A+B stage, k_lneg)
#define LSMEM  (3u * STB)            // 110592

#define AROWB  1040u                 // 512 halves + 16B pad (resident A, k_pred)
#define ARESB  (128u * AROWB)        // 133120
#define WSTB   MATB                  // 18432 per W stage
#define PSMEM  (ARESB + 3u * WSTB)   // 188416

// ---------------- shared compute fragments ----------------
// compute one 64-half ktile: A rows (strideA), B rows (ROWB) -> acc 32x64 per warp
__device__ __forceinline__ void compute_tile(uint32_t Ab, uint32_t strideA, uint32_t Bb,
                                             int wm, int wn, int lane, float acc[2][8][4]) {
    const uint32_t rlane = (uint32_t)(((lane >> 3) & 1) * 8 + (lane & 7));
    const uint32_t koffl = (uint32_t)(((lane >> 4) & 1) * 16);
#pragma unroll
    for (int kk = 0; kk < 4; kk++) {
        const uint32_t kb = (uint32_t)kk * 32u + koffl;
        uint32_t a[2][4];
#pragma unroll
        for (int mt = 0; mt < 2; mt++)
            ldsm4(Ab + (uint32_t)(wm * 32 + mt * 16) * strideA + rlane * strideA + kb,
                  a[mt][0], a[mt][1], a[mt][2], a[mt][3]);
        uint32_t b[4][4];
#pragma unroll
        for (int p = 0; p < 4; p++)
            ldsm4(Bb + (uint32_t)(wn * 64 + p * 16) * ROWB + rlane * ROWB + kb,
                  b[p][0], b[p][1], b[p][2], b[p][3]);
#pragma unroll
        for (int mt = 0; mt < 2; mt++)
#pragma unroll
            for (int nt = 0; nt < 8; nt++)
                mma16816(acc[mt][nt], a[mt], b[nt >> 1][nt & 1], b[nt >> 1][2 + (nt & 1)]);
    }
}

// ---------------- tiny helper kernels ----------------
__global__ void k_zero() { if (threadIdx.x < 2) g_cnt[threadIdx.x] = 0u; }

__global__ void k_ytrues(float* __restrict__ out) {
    long idx = (long)blockIdx.x * blockDim.x + threadIdx.x;
    if (idx < YTRUE_SIZE) out[YTRUE_OFF + idx] = (float)(idx / 2045);
}

__global__ void k_accs(float* __restrict__ out) {
    if (threadIdx.x == 0) out[ACC_OFF + 0] = (float)g_cnt[0] * (1.0f / (128.0f * 1023.0f));
    if (threadIdx.x == 1) out[ACC_OFF + 1] = (float)g_cnt[1] * (1.0f / (128.0f * 1022.0f));
}

__global__ void k_cvt_big(const float* __restrict__ ts, const float* __restrict__ pt) {
    const float* src = blockIdx.z ? pt : ts;
    __half* dst = blockIdx.z ? g_pt16 : g_ts16;
    const long n4 = 128l * 1024 * 512 / 4;
    long i = (long)blockIdx.x * blockDim.x + threadIdx.x;
    long stride = (long)gridDim.x * blockDim.x;
    for (; i < n4; i += stride) {
        float4 v = ((const float4*)src)[i];
        __half2 h0 = __floats2half2_rn(v.x, v.y);
        __half2 h1 = __floats2half2_rn(v.z, v.w);
        uint2 u;
        u.x = *reinterpret_cast<unsigned*>(&h0);
        u.y = *reinterpret_cast<unsigned*>(&h1);
        ((uint2*)dst)[i] = u;
    }
}

__global__ void k_cvt_w(const float* __restrict__ W1, const float* __restrict__ W2) {
    const float* src = blockIdx.z ? W2 : W1;
    __half* dst = g_w16 + (long)blockIdx.z * 262144;
    long i = (long)blockIdx.x * blockDim.x + threadIdx.x;   // 65536 float4s
    float4 v = ((const float4*)src)[i];
    __half2 h0 = __floats2half2_rn(v.x, v.y);
    __half2 h1 = __floats2half2_rn(v.z, v.w);
    uint2 u;
    u.x = *reinterpret_cast<unsigned*>(&h0);
    u.y = *reinterpret_cast<unsigned*>(&h1);
    ((uint2*)dst)[i] = u;
}

// ---------------- k_pred: resident-A, streamed W ----------------
// grid (128 m, 8 l0-blocks, 2 step). CTA: A = pt16[m][l0..l0+128][0..512] resident,
// stream 32 W tiles (4 c-blocks x 8 ktiles), epilogue per c-block.
__global__ __launch_bounds__(256, 1) void k_pred(const float* __restrict__ b1,
                                                 const float* __restrict__ b2) {
    extern __shared__ char dsm[];
    __shared__ float sb[512];
    const int tid = threadIdx.x;
    const int lane = tid & 31, wid = tid >> 5, wm = wid & 3, wn = wid >> 2;
    const int m = blockIdx.x;
    const int l0 = blockIdx.y * 128;
    const int step = blockIdx.z;
    const uint32_t Ares = s2u(dsm);
    const uint32_t Wst0 = Ares + ARESB;
    const __half* w16 = g_w16 + (long)step * 262144;
    const float* bias = step ? b2 : b1;

    sb[tid] = bias[tid];
    sb[tid + 256] = bias[tid + 256];

    // issue resident A (32 cp16/thread) as part of group 0
    // NOTE: aRow has NO embedded lane offset — seg alone selects the 16B segment.
    {
        const __half* aRow[4];
#pragma unroll
        for (int i = 0; i < 4; i++) {
            int r = (tid >> 3) + 32 * i;
            aRow[i] = g_pt16 + ((long)(m * 1024 + l0 + r)) * 512;
        }
#pragma unroll
        for (int i = 0; i < 4; i++) {
            uint32_t r = (uint32_t)(tid >> 3) + 32u * i;
#pragma unroll
            for (int j = 0; j < 8; j++) {
                uint32_t seg = (uint32_t)(tid & 7) + 8u * j;
                cp16(Ares + r * AROWB + seg * 16u, aRow[i] + seg * 8);
            }
        }
    }
    const __half* wRow[4];
#pragma unroll
    for (int i = 0; i < 4; i++)
        wRow[i] = w16 + ((long)((tid >> 3) + 32 * i)) * 512 + (tid & 7) * 8;
    const uint32_t wdst = (uint32_t)(tid >> 3) * ROWB + (uint32_t)(tid & 7) * 16u;

    // issue W stage gs: tile (cb = gs>>3, kt = gs&7): W rows cb*128+r, k-off kt*64
    auto issueW = [&](int gs) {
        uint32_t sbuf = Wst0 + (uint32_t)(gs % 3) * WSTB;
        long off = (long)(gs >> 3) * (128 * 512) + (long)(gs & 7) * 64;
#pragma unroll
        for (int i = 0; i < 4; i++)
            cp16(sbuf + (uint32_t)(32 * i) * ROWB + wdst, wRow[i] + off);
    };

    issueW(0); CP_COMMIT();          // group0 = A + W0
    issueW(1); CP_COMMIT();          // group1 = W1

    float acc[2][8][4] = {};
    for (int gs = 0; gs < 32; gs++) {
        if (gs < 31) CP_WAIT1(); else CP_WAIT0();
        __syncthreads();
        if (gs + 2 < 32) { issueW(gs + 2); CP_COMMIT(); }
        compute_tile(Ares + (uint32_t)(gs & 7) * 128u, AROWB,
                     Wst0 + (uint32_t)(gs % 3) * WSTB, wm, wn, lane, acc);
        if ((gs & 7) == 7) {
            // epilogue for c-block cb
            const int cb = gs >> 3;
#pragma unroll
            for (int mt = 0; mt < 2; mt++) {
                int mrow = wm * 32 + mt * 16 + (lane >> 2);
                long gr = ((long)(step * 128 + m)) * 1024 + l0 + mrow;
#pragma unroll
                for (int nt = 0; nt < 8; nt++) {
                    int cl = wn * 64 + nt * 8 + (lane & 3) * 2;
                    int gc = cb * 128 + cl;
                    __half2 h01 = __floats2half2_rn(acc[mt][nt][0] + sb[gc],
                                                    acc[mt][nt][1] + sb[gc + 1]);
                    *(__half2*)&g_pred16[gr * 512 + gc] = h01;
                    __half2 h23 = __floats2half2_rn(acc[mt][nt][2] + sb[gc],
                                                    acc[mt][nt][3] + sb[gc + 1]);
                    *(__half2*)&g_pred16[(gr + 8) * 512 + gc] = h23;
                    acc[mt][nt][0] = 0.f; acc[mt][nt][1] = 0.f;
                    acc[mt][nt][2] = 0.f; acc[mt][nt][3] = 0.f;
                }
            }
        }
    }
}

// ---------------- k_lneg: per-(l,step) 128(n)x128(m)x512 + accuracy + scratch ----------------
__global__ __launch_bounds__(256, 2) void k_lneg() {
    extern __shared__ char dsm[];
    const int tid = threadIdx.x;
    const int lane = tid & 31, wid = tid >> 5, wm = wid & 3, wn = wid >> 2;
    const int l = blockIdx.x;
    const int step = blockIdx.y;             // 0 or 1
    const int LS = 1023 - step;
    if (l >= LS) return;                     // uniform per CTA
    const uint32_t base = s2u(dsm);

    const __half* aP[4]; const __half* bP[4];
#pragma unroll
    for (int i = 0; i < 4; i++) {
        int r = (tid >> 3) + 32 * i;
        aP[i] = g_ts16 + ((long)(r * 1024) + l + step + 1) * 512 + (tid & 7) * 8;          // n rows
        bP[i] = g_pred16 + (((long)(step * 128 + r)) * 1024 + l) * 512 + (tid & 7) * 8;    // m rows
    }
    const uint32_t seg = (uint32_t)(tid & 7) * 16u;

    auto issue = [&](int kc) {
        uint32_t sbuf = base + (uint32_t)(kc % 3) * STB;
        int koff = kc * 64;
#pragma unroll
        for (int i = 0; i < 4; i++) {
            uint32_t r = (uint32_t)(tid >> 3) + 32u * i;
            cp16(sbuf + r * ROWB + seg, aP[i] + koff);
            cp16(sbuf + MATB + r * ROWB + seg, bP[i] + koff);
        }
    };

    issue(0); CP_COMMIT();
    issue(1); CP_COMMIT();

    float acc[2][8][4] = {};
#pragma unroll
    for (int kc = 0; kc < 8; kc++) {
        if (kc < 7) CP_WAIT1(); else CP_WAIT0();
        __syncthreads();
        if (kc + 2 < 8) { issue(kc + 2); CP_COMMIT(); }
        compute_tile(base + (uint32_t)(kc % 3) * STB, ROWB,
                     base + (uint32_t)(kc % 3) * STB + MATB, wm, wn, lane, acc);
    }
    __syncthreads();   // all warps done reading stages before sC overlay

    // stage D tile in smem for accuracy + coalesced scratch write
    float* sC = (float*)dsm;  // [128][129]
#pragma unroll
    for (int mt = 0; mt < 2; mt++) {
        int n = wm * 32 + mt * 16 + (lane >> 2);
#pragma unroll
        for (int nt = 0; nt < 8; nt++) {
            int mc = wn * 64 + nt * 8 + (lane & 3) * 2;
            sC[n * 129 + mc]           = acc[mt][nt][0];
            sC[n * 129 + mc + 1]       = acc[mt][nt][1];
            sC[(n + 8) * 129 + mc]     = acc[mt][nt][2];
            sC[(n + 8) * 129 + mc + 1] = acc[mt][nt][3];
        }
    }
    __syncthreads();

    if (tid < 128) {
        float pos = sC[tid * 129 + tid];
        bool win = true;
#pragma unroll 8
        for (int mm = 0; mm < 128; mm++)
            if (mm != tid && !(pos > sC[tid * 129 + mm])) win = false;
        unsigned bal = __ballot_sync(0xffffffffu, win);
        if ((tid & 31) == 0) atomicAdd(&g_cnt[step], (unsigned)__popc(bal));
    }

    const float invT = 1.0f / 0.07f;
    const long gl = (long)step * 1023 + l;
    for (int idx = tid; idx < 128 * 128; idx += 256) {
        int n = idx >> 7, mm = idx & 127;
        g_lneg[gl * 16384 + idx] = sC[n * 129 + mm] * invT;
    }
}

// ---------------- k_tr: scratch [gl][nm] -> out [nm][gl] ----------------
__global__ __launch_bounds__(256) void k_tr(float* __restrict__ out) {
    __shared__ float t[32][257];
    const int tid = threadIdx.x;
    const int nm0 = blockIdx.x * 256;
    const int gl0 = blockIdx.y * 32;
#pragma unroll 4
    for (int i = 0; i < 32; i++) {
        int gl = gl0 + i;
        if (gl < 2045) t[i][tid] = g_lneg[(long)gl * 16384 + nm0 + tid];
    }
    __syncthreads();
    const int w = tid >> 5, lane = tid & 31;
    const int gl = gl0 + lane;
    if (gl < 2045) {
#pragma unroll 4
        for (int q = 0; q < 32; q++) {
            int nm = w * 32 + q;
            out[(long)(nm0 + nm) * 2045 + gl] = t[lane][nm];
        }
    }
}

// ---------------- launch ----------------
extern "C" void kernel_launch(void* const* d_in, const int* in_sizes, int n_in,
                              void* d_out, int out_size) {
    const float* ts = (const float*)d_in[0];
    const float* pt = (const float*)d_in[1];
    const float* W1 = (const float*)d_in[2];
    const float* b1 = (const float*)d_in[3];
    const float* W2 = (const float*)d_in[4];
    const float* b2 = (const float*)d_in[5];
    float* out = (float*)d_out;

    cudaFuncSetAttribute(k_pred, cudaFuncAttributeMaxDynamicSharedMemorySize, PSMEM);
    cudaFuncSetAttribute(k_lneg, cudaFuncAttributeMaxDynamicSharedMemorySize, LSMEM);

    k_zero<<<1, 32>>>();
    k_ytrues<<<(int)((YTRUE_SIZE + 255) / 256), 256>>>(out);

    k_cvt_big<<<dim3(16384, 1, 2), 256>>>(ts, pt);
    k_cvt_w<<<dim3(256, 1, 2), 256>>>(W1, W2);

    k_pred<<<dim3(128, 8, 2), 256, PSMEM>>>(b1, b2);
    k_lneg<<<dim3(1023, 2), 256, LSMEM>>>();
    k_tr<<<dim3(64, 64), 256>>>(out);

    k_accs<<<1, 32>>>(out);
}

// round 7
// speedup vs baseline: 1.1388x; 1.1388x over previous
#include <cuda_runtime.h>
#include <cuda_fp16.h>
#include <cstdint>

// ---------------- problem constants ----------------
#define YTRUE_OFF  33505280l
#define YTRUE_SIZE 261760l
#define ACC_OFF    33767040l

// ---------------- scratch (__device__ globals; no allocs allowed) ----------------
static __device__ __half g_ts16[128ll * 1024 * 512];        // timesteps f16
static __device__ __half g_pt16[128ll * 1024 * 512];        // patient f16
static __device__ __half g_pred16[2ll * 128 * 1024 * 512];  // pred f16 [step][m][l][c]
static __device__ __half g_w16[2ll * 512 * 512];            // W1,W2 f16
static __device__ float  g_lneg[2045ll * 128 * 128];        // [gl][n*128+m]
static __device__ unsigned int g_cnt[2];

// ---------------- PTX helpers (family-portable; no tcgen05) ----------------
__device__ __forceinline__ uint32_t s2u(const void* p) {
    uint32_t a;
    asm("{ .reg .u64 t; cvta.to.shared.u64 t, %1; cvt.u32.u64 %0, t; }" : "=r"(a) : "l"(p));
    return a;
}
__device__ __forceinline__ void cp16(uint32_t dst, const void* src) {
    asm volatile("cp.async.cg.shared.global [%0], [%1], 16;" :: "r"(dst), "l"(src));
}
#define CP_COMMIT() asm volatile("cp.async.commit_group;" ::: "memory")
#define CP_WAIT1()  asm volatile("cp.async.wait_group 1;" ::: "memory")
#define CP_WAIT0()  asm volatile("cp.async.wait_group 0;" ::: "memory")

__device__ __forceinline__ void ldsm4(uint32_t addr, uint32_t& r0, uint32_t& r1,
                                      uint32_t& r2, uint32_t& r3) {
    asm volatile("ldmatrix.sync.aligned.m8n8.x4.shared.b16 {%0,%1,%2,%3}, [%4];"
                 : "=r"(r0), "=r"(r1), "=r"(r2), "=r"(r3) : "r"(addr));
}
__device__ __forceinline__ void mma16816(float* d, const uint32_t* a, uint32_t b0, uint32_t b1) {
    asm volatile(
        "mma.sync.aligned.m16n8k16.row.col.f32.f16.f16.f32 "
        "{%0,%1,%2,%3}, {%4,%5,%6,%7}, {%8,%9}, {%0,%1,%2,%3};"
        : "+f"(d[0]), "+f"(d[1]), "+f"(d[2]), "+f"(d[3])
        : "r"(a[0]), "r"(a[1]), "r"(a[2]), "r"(a[3]), "r"(b0), "r"(b1));
}

// ---------------- stage geometry ----------------
#define ROWB   144u                  // 64 halves + 16B pad
#define MATB   (128u * ROWB)         // 18432
#define STB    (2u * MATB)           // 36864 (A+B per stage)
#define GSMEM  (3u * STB)            // 110592 -> occ 2

// ---------------- shared compute fragment ----------------
// one 64-half ktile: A rows + B rows (both ROWB stride) -> acc 32x64 per warp
__device__ __forceinline__ void compute_tile(uint32_t Ab, uint32_t Bb,
                                             int wm, int wn, int lane, float acc[2][8][4]) {
    const uint32_t rlane = (uint32_t)(((lane >> 3) & 1) * 8 + (lane & 7));
    const uint32_t koffl = (uint32_t)(((lane >> 4) & 1) * 16);
#pragma unroll
    for (int kk = 0; kk < 4; kk++) {
        const uint32_t kb = (uint32_t)kk * 32u + koffl;
        uint32_t a[2][4];
#pragma unroll
        for (int mt = 0; mt < 2; mt++)
            ldsm4(Ab + (uint32_t)(wm * 32 + mt * 16) * ROWB + rlane * ROWB + kb,
                  a[mt][0], a[mt][1], a[mt][2], a[mt][3]);
        uint32_t b[4][4];
#pragma unroll
        for (int p = 0; p < 4; p++)
            ldsm4(Bb + (uint32_t)(wn * 64 + p * 16) * ROWB + rlane * ROWB + kb,
                  b[p][0], b[p][1], b[p][2], b[p][3]);
#pragma unroll
        for (int mt = 0; mt < 2; mt++)
#pragma unroll
            for (int nt = 0; nt < 8; nt++)
                mma16816(acc[mt][nt], a[mt], b[nt >> 1][nt & 1], b[nt >> 1][2 + (nt & 1)]);
    }
}

// ---------------- tiny helper kernels ----------------
__global__ void k_zero() { if (threadIdx.x < 2) g_cnt[threadIdx.x] = 0u; }

__global__ void k_ytrues(float* __restrict__ out) {
    long idx = (long)blockIdx.x * blockDim.x + threadIdx.x;
    if (idx < YTRUE_SIZE) out[YTRUE_OFF + idx] = (float)(idx / 2045);
}

__global__ void k_accs(float* __restrict__ out) {
    if (threadIdx.x == 0) out[ACC_OFF + 0] = (float)g_cnt[0] * (1.0f / (128.0f * 1023.0f));
    if (threadIdx.x == 1) out[ACC_OFF + 1] = (float)g_cnt[1] * (1.0f / (128.0f * 1022.0f));
}

__global__ void k_cvt_big(const float* __restrict__ ts, const float* __restrict__ pt) {
    const float* src = blockIdx.z ? pt : ts;
    __half* dst = blockIdx.z ? g_pt16 : g_ts16;
    const long n4 = 128l * 1024 * 512 / 4;
    long i = (long)blockIdx.x * blockDim.x + threadIdx.x;
    long stride = (long)gridDim.x * blockDim.x;
    for (; i < n4; i += stride) {
        float4 v = ((const float4*)src)[i];
        __half2 h0 = __floats2half2_rn(v.x, v.y);
        __half2 h1 = __floats2half2_rn(v.z, v.w);
        uint2 u;
        u.x = *reinterpret_cast<unsigned*>(&h0);
        u.y = *reinterpret_cast<unsigned*>(&h1);
        ((uint2*)dst)[i] = u;
    }
}

__global__ void k_cvt_w(const float* __restrict__ W1, const float* __restrict__ W2) {
    const float* src = blockIdx.z ? W2 : W1;
    __half* dst = g_w16 + (long)blockIdx.z * 262144;
    long i = (long)blockIdx.x * blockDim.x + threadIdx.x;   // 65536 float4s
    float4 v = ((const float4*)src)[i];
    __half2 h0 = __floats2half2_rn(v.x, v.y);
    __half2 h1 = __floats2half2_rn(v.z, v.w);
    uint2 u;
    u.x = *reinterpret_cast<unsigned*>(&h0);
    u.y = *reinterpret_cast<unsigned*>(&h1);
    ((uint2*)dst)[i] = u;
}

// ---------------- k_pred: R3 tiling, merged steps, single-sync mainloop ----------------
// grid (4 cb, 8 l0blk, 256 = step*128+m). CTA: C tile rows = 128 l's (contiguous),
// cols = 128 c's. A = pt16 rows, B = W rows, both streamed 3-stage.
__global__ __launch_bounds__(256, 2) void k_pred(const float* __restrict__ b1,
                                                 const float* __restrict__ b2) {
    extern __shared__ char dsm[];
    __shared__ float sb[128];
    const int tid = threadIdx.x;
    const int lane = tid & 31, wid = tid >> 5, wm = wid & 3, wn = wid >> 2;
    const int cb = blockIdx.x;
    const int l0 = blockIdx.y * 128;
    const int step = blockIdx.z >> 7;
    const int m = blockIdx.z & 127;
    const uint32_t base = s2u(dsm);
    const __half* w16 = g_w16 + (long)step * 262144;
    const float* bias = step ? b2 : b1;

    if (tid < 128) sb[tid] = bias[cb * 128 + tid];

    const __half* aP[4]; const __half* bP[4];
#pragma unroll
    for (int i = 0; i < 4; i++) {
        int r = (tid >> 3) + 32 * i;
        aP[i] = g_pt16 + ((long)(m * 1024 + l0 + r)) * 512 + (tid & 7) * 8;
        bP[i] = w16 + ((long)(cb * 128 + r)) * 512 + (tid & 7) * 8;
    }
    const uint32_t seg = (uint32_t)(tid & 7) * 16u;

    auto issue = [&](int kc) {
        uint32_t sbuf = base + (uint32_t)(kc % 3) * STB;
        int koff = kc * 64;
#pragma unroll
        for (int i = 0; i < 4; i++) {
            uint32_t r = (uint32_t)(tid >> 3) + 32u * i;
            cp16(sbuf + r * ROWB + seg, aP[i] + koff);
            cp16(sbuf + MATB + r * ROWB + seg, bP[i] + koff);
        }
    };

    issue(0); CP_COMMIT();
    issue(1); CP_COMMIT();

    float acc[2][8][4] = {};
#pragma unroll
    for (int kc = 0; kc < 8; kc++) {
        if (kc < 7) CP_WAIT1(); else CP_WAIT0();
        __syncthreads();
        if (kc + 2 < 8) { issue(kc + 2); CP_COMMIT(); }
        compute_tile(base + (uint32_t)(kc % 3) * STB,
                     base + (uint32_t)(kc % 3) * STB + MATB, wm, wn, lane, acc);
    }

    // epilogue: +bias, f16 store to g_pred16[step][m][l0+row][cb*128+cl]
#pragma unroll
    for (int mt = 0; mt < 2; mt++) {
        int mrow = wm * 32 + mt * 16 + (lane >> 2);
        long gr = ((long)(step * 128 + m)) * 1024 + l0 + mrow;
#pragma unroll
        for (int nt = 0; nt < 8; nt++) {
            int cl = wn * 64 + nt * 8 + (lane & 3) * 2;
            __half2 h01 = __floats2half2_rn(acc[mt][nt][0] + sb[cl],
                                            acc[mt][nt][1] + sb[cl + 1]);
            *(__half2*)&g_pred16[gr * 512 + cb * 128 + cl] = h01;
            __half2 h23 = __floats2half2_rn(acc[mt][nt][2] + sb[cl],
                                            acc[mt][nt][3] + sb[cl + 1]);
            *(__half2*)&g_pred16[(gr + 8) * 512 + cb * 128 + cl] = h23;
        }
    }
}

// ---------------- k_lneg: per-(l,step) 128(n)x128(m)x512 + accuracy + scratch ----------------
__global__ __launch_bounds__(256, 2) void k_lneg() {
    extern __shared__ char dsm[];
    const int tid = threadIdx.x;
    const int lane = tid & 31, wid = tid >> 5, wm = wid & 3, wn = wid >> 2;
    const int l = blockIdx.x;
    const int step = blockIdx.y;             // 0 or 1
    const int LS = 1023 - step;
    if (l >= LS) return;                     // uniform per CTA
    const uint32_t base = s2u(dsm);

    const __half* aP[4]; const __half* bP[4];
#pragma unroll
    for (int i = 0; i < 4; i++) {
        int r = (tid >> 3) + 32 * i;
        aP[i] = g_ts16 + ((long)(r * 1024) + l + step + 1) * 512 + (tid & 7) * 8;          // n rows
        bP[i] = g_pred16 + (((long)(step * 128 + r)) * 1024 + l) * 512 + (tid & 7) * 8;    // m rows
    }
    const uint32_t seg = (uint32_t)(tid & 7) * 16u;

    auto issue = [&](int kc) {
        uint32_t sbuf = base + (uint32_t)(kc % 3) * STB;
        int koff = kc * 64;
#pragma unroll
        for (int i = 0; i < 4; i++) {
            uint32_t r = (uint32_t)(tid >> 3) + 32u * i;
            cp16(sbuf + r * ROWB + seg, aP[i] + koff);
            cp16(sbuf + MATB + r * ROWB + seg, bP[i] + koff);
        }
    };

    issue(0); CP_COMMIT();
    issue(1); CP_COMMIT();

    float acc[2][8][4] = {};
#pragma unroll
    for (int kc = 0; kc < 8; kc++) {
        if (kc < 7) CP_WAIT1(); else CP_WAIT0();
        __syncthreads();
        if (kc + 2 < 8) { issue(kc + 2); CP_COMMIT(); }
        compute_tile(base + (uint32_t)(kc % 3) * STB,
                     base + (uint32_t)(kc % 3) * STB + MATB, wm, wn, lane, acc);
    }
    __syncthreads();   // all warps done reading stages before sC overlay

    // stage D tile in smem for accuracy + coalesced scratch write
    float* sC = (float*)dsm;  // [128][129]
#pragma unroll
    for (int mt = 0; mt < 2; mt++) {
        int n = wm * 32 + mt * 16 + (lane >> 2);
#pragma unroll
        for (int nt = 0; nt < 8; nt++) {
            int mc = wn * 64 + nt * 8 + (lane & 3) * 2;
            sC[n * 129 + mc]           = acc[mt][nt][0];
            sC[n * 129 + mc + 1]       = acc[mt][nt][1];
            sC[(n + 8) * 129 + mc]     = acc[mt][nt][2];
            sC[(n + 8) * 129 + mc + 1] = acc[mt][nt][3];
        }
    }
    __syncthreads();

    if (tid < 128) {
        float pos = sC[tid * 129 + tid];
        bool win = true;
#pragma unroll 8
        for (int mm = 0; mm < 128; mm++)
            if (mm != tid && !(pos > sC[tid * 129 + mm])) win = false;
        unsigned bal = __ballot_sync(0xffffffffu, win);
        if ((tid & 31) == 0) atomicAdd(&g_cnt[step], (unsigned)__popc(bal));
    }

    const float invT = 1.0f / 0.07f;
    const long gl = (long)step * 1023 + l;
    for (int idx = tid; idx < 128 * 128; idx += 256) {
        int n = idx >> 7, mm = idx & 127;
        g_lneg[gl * 16384 + idx] = sC[n * 129 + mm] * invT;
    }
}

// ---------------- k_tr: scratch [gl][nm] -> out [nm][gl] ----------------
__global__ __launch_bounds__(256) void k_tr(float* __restrict__ out) {
    __shared__ float t[32][257];
    const int tid = threadIdx.x;
    const int nm0 = blockIdx.x * 256;
    const int gl0 = blockIdx.y * 32;
#pragma unroll 4
    for (int i = 0; i < 32; i++) {
        int gl = gl0 + i;
        if (gl < 2045) t[i][tid] = g_lneg[(long)gl * 16384 + nm0 + tid];
    }
    __syncthreads();
    const int w = tid >> 5, lane = tid & 31;
    const int gl = gl0 + lane;
    if (gl < 2045) {
#pragma unroll 4
        for (int q = 0; q < 32; q++) {
            int nm = w * 32 + q;
            out[(long)(nm0 + nm) * 2045 + gl] = t[lane][nm];
        }
    }
}

// ---------------- launch ----------------
extern "C" void kernel_launch(void* const* d_in, const int* in_sizes, int n_in,
                              void* d_out, int out_size) {
    const float* ts = (const float*)d_in[0];
    const float* pt = (const float*)d_in[1];
    const float* W1 = (const float*)d_in[2];
    const float* b1 = (const float*)d_in[3];
    const float* W2 = (const float*)d_in[4];
    const float* b2 = (const float*)d_in[5];
    float* out = (float*)d_out;

    cudaFuncSetAttribute(k_pred, cudaFuncAttributeMaxDynamicSharedMemorySize, GSMEM);
    cudaFuncSetAttribute(k_lneg, cudaFuncAttributeMaxDynamicSharedMemorySize, GSMEM);

    k_zero<<<1, 32>>>();
    k_ytrues<<<(int)((YTRUE_SIZE + 255) / 256), 256>>>(out);

    k_cvt_w<<<dim3(256, 1, 2), 256>>>(W1, W2);
    k_cvt_big<<<dim3(16384, 1, 2), 256>>>(ts, pt);

    k_pred<<<dim3(4, 8, 256), 256, GSMEM>>>(b1, b2);
    k_lneg<<<dim3(1023, 2), 256, GSMEM>>>();
    k_tr<<<dim3(64, 64), 256>>>(out);

    k_accs<<<1, 32>>>(out);
}